// round 2
// baseline (speedup 1.0000x reference)
#include <cuda_runtime.h>
#include <math.h>

// RotorQuantMSE — R2: register-resident, smem-free data path.
// Each thread owns 4 consecutive groups (12 floats = 3 aligned float4s).
// 64 threads per row, 256-thread block = 4 rows per iteration, grid-stride loop
// so per-thread rotor registers (4 rotors) are reused across rows.

#define NBLK 592        // 148 SMs * 4 blocks

__device__ __forceinline__ void rotor_apply(
    float r0, float b1, float b2, float b3,
    float v1, float v2, float v3,
    float& o1, float& o2, float& o3)
{
    // t = R * v (geometric product, v pure vector); u = t * ~R (grade-1 part)
    float t1 = fmaf(r0, v1, fmaf(b1, v2,  b2 * v3));
    float t2 = fmaf(r0, v2, fmaf(-b1, v1, b3 * v3));
    float t3 = fmaf(r0, v3, fmaf(-b2, v1, -b3 * v2));
    float t7 = fmaf(b1, v3, fmaf(-b2, v2,  b3 * v1));
    o1 = fmaf(r0, t1, fmaf( b1, t2, fmaf( b2, t3,  b3 * t7)));
    o2 = fmaf(r0, t2, fmaf(-b1, t1, fmaf( b3, t3, -b2 * t7)));
    o3 = fmaf(r0, t3, fmaf(-b2, t1, fmaf(-b3, t2,  b1 * t7)));
}

__global__ void __launch_bounds__(256)
rotor_quant_kernel(const float* __restrict__ x,
                   const float* __restrict__ rotors,
                   float* __restrict__ xhat,
                   float* __restrict__ idx_out,
                   float* __restrict__ norms_out,
                   int N)
{
    const int tid = threadIdx.x;
    const int s   = tid >> 6;        // sub-row within block, 0..3
    const int t   = tid & 63;        // thread within row, 0..63
    const int wid = tid >> 5;        // warp id, 0..7

    __shared__ float spart[8];

    // rotors for groups 4t .. 4t+3, loaded once and kept in registers
    float r0[4], b1[4], b2[4], b3[4];
#pragma unroll
    for (int k = 0; k < 4; k++) {
        const float* rp = rotors + (((4 * t + k)) << 3);
        r0[k] = __ldg(rp);
        float4 bv = __ldg(reinterpret_cast<const float4*>(rp + 4));
        b1[k] = bv.x; b2[k] = bv.y; b3[k] = bv.z;
    }

    const float step = 2.0f / 15.0f;     // centroid spacing, linspace(-1,1,16)

    for (int base = blockIdx.x * 4; base < N; base += NBLK * 4) {
        const int row = base + s;        // always < N when N % 4 == 0; guarded anyway
        const bool active = (row < N);

        float vin[12];
        if (active) {
            const float4* px = reinterpret_cast<const float4*>(x + (size_t)row * 768);
            float4 a0 = __ldg(px + 3 * t + 0);
            float4 a1 = __ldg(px + 3 * t + 1);
            float4 a2 = __ldg(px + 3 * t + 2);
            vin[0]=a0.x; vin[1]=a0.y; vin[2]=a0.z;  vin[3]=a0.w;
            vin[4]=a1.x; vin[5]=a1.y; vin[6]=a1.z;  vin[7]=a1.w;
            vin[8]=a2.x; vin[9]=a2.y; vin[10]=a2.z; vin[11]=a2.w;
        } else {
#pragma unroll
            for (int i = 0; i < 12; i++) vin[i] = 0.0f;
        }

        // row L2 norm: warp reduce, combine 2 warps per row via smem
        float sq = 0.0f;
#pragma unroll
        for (int i = 0; i < 12; i++) sq = fmaf(vin[i], vin[i], sq);
#pragma unroll
        for (int o = 16; o; o >>= 1) sq += __shfl_xor_sync(0xffffffffu, sq, o);
        if ((tid & 31) == 0) spart[wid] = sq;
        __syncthreads();
        float tot = spart[2 * s] + spart[2 * s + 1];
        __syncthreads();                 // spart reused next iteration

        const float nrm = fmaxf(sqrtf(tot), 1e-8f);
        const float inv = 1.0f / nrm;

        float vout[12], fidx[12];
#pragma unroll
        for (int g = 0; g < 4; g++) {
            float y1, y2, y3;
            rotor_apply(r0[g], b1[g], b2[g], b3[g],
                        vin[3*g + 0] * inv, vin[3*g + 1] * inv, vin[3*g + 2] * inv,
                        y1, y2, y3);
            // argmin |y - c_k|, ties -> lower index:
            // u = (y+1)*7.5 ; k = clamp(ceil(u - 0.5), 0, 15)
            int k1 = max(0, min(15, (int)ceilf(fmaf(y1 + 1.0f, 7.5f, -0.5f))));
            int k2 = max(0, min(15, (int)ceilf(fmaf(y2 + 1.0f, 7.5f, -0.5f))));
            int k3 = max(0, min(15, (int)ceilf(fmaf(y3 + 1.0f, 7.5f, -0.5f))));
            float q1 = fmaf((float)k1, step, -1.0f);
            float q2 = fmaf((float)k2, step, -1.0f);
            float q3 = fmaf((float)k3, step, -1.0f);
            float h1, h2, h3;
            rotor_apply(r0[g], -b1[g], -b2[g], -b3[g], q1, q2, q3, h1, h2, h3);
            vout[3*g + 0] = h1 * nrm;
            vout[3*g + 1] = h2 * nrm;
            vout[3*g + 2] = h3 * nrm;
            fidx[3*g + 0] = (float)k1;
            fidx[3*g + 1] = (float)k2;
            fidx[3*g + 2] = (float)k3;
        }

        if (active) {
            float4* ph = reinterpret_cast<float4*>(xhat + (size_t)row * 768);
            ph[3*t + 0] = make_float4(vout[0], vout[1], vout[2],  vout[3]);
            ph[3*t + 1] = make_float4(vout[4], vout[5], vout[6],  vout[7]);
            ph[3*t + 2] = make_float4(vout[8], vout[9], vout[10], vout[11]);
            if (idx_out) {
                float4* pi = reinterpret_cast<float4*>(idx_out + (size_t)row * 768);
                pi[3*t + 0] = make_float4(fidx[0], fidx[1], fidx[2],  fidx[3]);
                pi[3*t + 1] = make_float4(fidx[4], fidx[5], fidx[6],  fidx[7]);
                pi[3*t + 2] = make_float4(fidx[8], fidx[9], fidx[10], fidx[11]);
            }
            if (t == 0 && norms_out) norms_out[row] = nrm;
        }
    }
}

extern "C" void kernel_launch(void* const* d_in, const int* in_sizes, int n_in,
                              void* d_out, int out_size)
{
    const float* x      = (const float*)d_in[0];   // [N, d]
    const float* rotors = (const float*)d_in[2];   // [G, 8]

    const int G = in_sizes[2] / 8;        // 256
    const int d = 3 * G;                  // 768
    const int N = in_sizes[0] / d;        // 8192

    float* out   = (float*)d_out;
    float* xhat  = out;
    float* idxp  = nullptr;
    float* normp = nullptr;
    const long nd = (long)N * d;
    if ((long)out_size >= 2 * nd)     idxp  = out + nd;
    if ((long)out_size >= 2 * nd + N) normp = out + 2 * nd;

    rotor_quant_kernel<<<NBLK, 256>>>(x, rotors, xhat, idxp, normp, N);
}

// round 3
// speedup vs baseline: 1.1810x; 1.1810x over previous
#include <cuda_runtime.h>
#include <math.h>

// RotorQuantMSE — R3: dense coalesced float4 per thread + 4-shuffle boundary
// exchange (a float4 spans exactly 2 groups of 3). Persistent blocks keep the
// two per-thread 3x3 rotation matrices (from the rotor sandwich) in registers.
// Inverse rotation = matrix transpose. 192 threads = 6 warps = 1 row (768 f32).

#define D 768
#define NBLK 1184   // 148 SMs * 8

__device__ __forceinline__ void rotor_apply(
    float r0, float b1, float b2, float b3,
    float v1, float v2, float v3,
    float& o1, float& o2, float& o3)
{
    float t1 = fmaf(r0, v1, fmaf(b1, v2,  b2 * v3));
    float t2 = fmaf(r0, v2, fmaf(-b1, v1, b3 * v3));
    float t3 = fmaf(r0, v3, fmaf(-b2, v1, -b3 * v2));
    float t7 = fmaf(b1, v3, fmaf(-b2, v2,  b3 * v1));
    o1 = fmaf(r0, t1, fmaf( b1, t2, fmaf( b2, t3,  b3 * t7)));
    o2 = fmaf(r0, t2, fmaf(-b1, t1, fmaf( b3, t3, -b2 * t7)));
    o3 = fmaf(r0, t3, fmaf(-b2, t1, fmaf(-b3, t2,  b1 * t7)));
}

__device__ __forceinline__ void build_mat(const float* __restrict__ rp, float M[9])
{
    float r0 = __ldg(rp + 0);
    float4 bv = __ldg(reinterpret_cast<const float4*>(rp + 4));
    float b1 = bv.x, b2 = bv.y, b3 = bv.z;
    // columns of M = sandwich applied to e1, e2, e3 ; y_i = sum_j M[3i+j] v_j
    rotor_apply(r0, b1, b2, b3, 1.f, 0.f, 0.f, M[0], M[3], M[6]);
    rotor_apply(r0, b1, b2, b3, 0.f, 1.f, 0.f, M[1], M[4], M[7]);
    rotor_apply(r0, b1, b2, b3, 0.f, 0.f, 1.f, M[2], M[5], M[8]);
}

__device__ __forceinline__ int quant(float y)
{
    int k = (int)ceilf(fmaf(y + 1.0f, 7.5f, -0.5f));
    return max(0, min(15, k));
}

__global__ void __launch_bounds__(192, 5)
rotor_quant_kernel(const float* __restrict__ x,
                   const float* __restrict__ rotors,
                   float* __restrict__ xhat,
                   float* __restrict__ idx_out,
                   float* __restrict__ norms_out,
                   int N)
{
    const int w = threadIdx.x >> 5;      // warp 0..5
    const int l = threadIdx.x & 31;
    const int p0 = 128 * w + 4 * l;      // first float position in row
    const int m  = p0 % 3;               // alignment within group
    const int gA = p0 / 3;               // first overlapped group (gB = gA+1)
    const int f4 = 32 * w + l;           // float4 index within row

    // this thread's two rotation matrices, fixed across all rows
    float MA[9], MB[9];
    build_mat(rotors + (size_t)gA * 8, MA);
    build_mat(rotors + (size_t)(gA + 1) * 8, MB);

    // boundary predicates: lane0 needs 2 floats before its warp's 128-float
    // region unless the region starts on a group boundary; lane31 symmetric.
    const bool needPrev = (l == 0)  && ((128 * w) % 3 != 0);
    const bool needNext = (l == 31) && ((128 * (w + 1)) % 3 != 0);

    __shared__ __align__(16) float spart[2][8];
    const float step = 2.0f / 15.0f;

    // prologue loads for first row
    int row = blockIdx.x;
    float4 a = make_float4(0, 0, 0, 0);
    float2 pv = make_float2(0, 0), nx = make_float2(0, 0);
    if (row < N) {
        const float* xr = x + (size_t)row * D;
        a = __ldg(reinterpret_cast<const float4*>(xr) + f4);
        if (needPrev) pv = __ldg(reinterpret_cast<const float2*>(xr + 128 * w - 2));
        if (needNext) nx = __ldg(reinterpret_cast<const float2*>(xr + 128 * (w + 1)));
    }

    int buf = 0;
    for (; row < N; row += gridDim.x) {
        // norm partial from own float4 (each float counted exactly once)
        float sq = fmaf(a.x, a.x, fmaf(a.y, a.y, fmaf(a.z, a.z, a.w * a.w)));
        #pragma unroll
        for (int o = 16; o; o >>= 1) sq += __shfl_xor_sync(0xffffffffu, sq, o);
        if (l == 0) spart[buf][w] = sq;

        // prefetch next row before the barrier to hide DRAM latency
        const int nrow = row + gridDim.x;
        float4 a2 = make_float4(0, 0, 0, 0);
        float2 pv2 = make_float2(0, 0), nx2 = make_float2(0, 0);
        if (nrow < N) {
            const float* xr2 = x + (size_t)nrow * D;
            a2 = __ldg(reinterpret_cast<const float4*>(xr2) + f4);
            if (needPrev) pv2 = __ldg(reinterpret_cast<const float2*>(xr2 + 128 * w - 2));
            if (needNext) nx2 = __ldg(reinterpret_cast<const float2*>(xr2 + 128 * (w + 1)));
        }

        __syncthreads();
        float4 s4 = *reinterpret_cast<float4*>(spart[buf]);
        float2 s2 = *reinterpret_cast<float2*>(spart[buf] + 4);
        buf ^= 1;
        const float nrm = fmaxf(sqrtf(s4.x + s4.y + s4.z + s4.w + s2.x + s2.y), 1e-8f);
        const float inv = 1.0f / nrm;

        // neighbor exchange: e[k] = row float at p0-2+k
        float e0 = __shfl_up_sync(0xffffffffu, a.z, 1);
        float e1 = __shfl_up_sync(0xffffffffu, a.w, 1);
        float e6 = __shfl_down_sync(0xffffffffu, a.x, 1);
        float e7 = __shfl_down_sync(0xffffffffu, a.y, 1);
        if (l == 0)  { e0 = pv.x; e1 = pv.y; }
        if (l == 31) { e6 = nx.x; e7 = nx.y; }
        const float e2 = a.x, e3 = a.y, e4 = a.z, e5 = a.w;

        // group inputs: vA starts at e[2-m], vB at e[5-m]
        float vA0 = (m == 0) ? e2 : (m == 1) ? e1 : e0;
        float vA1 = (m == 0) ? e3 : (m == 1) ? e2 : e1;
        float vA2 = (m == 0) ? e4 : (m == 1) ? e3 : e2;
        float vB0 = (m == 0) ? e5 : (m == 1) ? e4 : e3;
        float vB1 = (m == 0) ? e6 : (m == 1) ? e5 : e4;
        float vB2 = (m == 0) ? e7 : (m == 1) ? e6 : e5;

        // forward rotation of normalized vectors
        float yA0 = fmaf(MA[0], vA0, fmaf(MA[1], vA1, MA[2] * vA2)) * inv;
        float yA1 = fmaf(MA[3], vA0, fmaf(MA[4], vA1, MA[5] * vA2)) * inv;
        float yA2 = fmaf(MA[6], vA0, fmaf(MA[7], vA1, MA[8] * vA2)) * inv;
        float yB0 = fmaf(MB[0], vB0, fmaf(MB[1], vB1, MB[2] * vB2)) * inv;
        float yB1 = fmaf(MB[3], vB0, fmaf(MB[4], vB1, MB[5] * vB2)) * inv;
        float yB2 = fmaf(MB[6], vB0, fmaf(MB[7], vB1, MB[8] * vB2)) * inv;

        // quantize / dequantize (centroids = linspace(-1,1,16))
        int kA0 = quant(yA0), kA1 = quant(yA1), kA2 = quant(yA2);
        int kB0 = quant(yB0), kB1 = quant(yB1), kB2 = quant(yB2);
        float qA0 = fmaf((float)kA0, step, -1.0f);
        float qA1 = fmaf((float)kA1, step, -1.0f);
        float qA2 = fmaf((float)kA2, step, -1.0f);
        float qB0 = fmaf((float)kB0, step, -1.0f);
        float qB1 = fmaf((float)kB1, step, -1.0f);
        float qB2 = fmaf((float)kB2, step, -1.0f);

        // inverse rotation = M^T, rescale by nrm
        float hA0 = fmaf(MA[0], qA0, fmaf(MA[3], qA1, MA[6] * qA2)) * nrm;
        float hA1 = fmaf(MA[1], qA0, fmaf(MA[4], qA1, MA[7] * qA2)) * nrm;
        float hA2 = fmaf(MA[2], qA0, fmaf(MA[5], qA1, MA[8] * qA2)) * nrm;
        float hB0 = fmaf(MB[0], qB0, fmaf(MB[3], qB1, MB[6] * qB2)) * nrm;
        float hB1 = fmaf(MB[1], qB0, fmaf(MB[4], qB1, MB[7] * qB2)) * nrm;
        float hB2 = fmaf(MB[2], qB0, fmaf(MB[5], qB1, MB[8] * qB2)) * nrm;

        // select the 4 output components: position p0+j -> component (m+j),
        // in group A if m+j < 3 else group B component m+j-3
        float4 oh, oi;
        oh.x = (m == 0) ? hA0 : (m == 1) ? hA1 : hA2;
        oh.y = (m == 0) ? hA1 : (m == 1) ? hA2 : hB0;
        oh.z = (m == 0) ? hA2 : (m == 1) ? hB0 : hB1;
        oh.w = (m == 0) ? hB0 : (m == 1) ? hB1 : hB2;
        oi.x = (float)((m == 0) ? kA0 : (m == 1) ? kA1 : kA2);
        oi.y = (float)((m == 0) ? kA1 : (m == 1) ? kA2 : kB0);
        oi.z = (float)((m == 0) ? kA2 : (m == 1) ? kB0 : kB1);
        oi.w = (float)((m == 0) ? kB0 : (m == 1) ? kB1 : kB2);

        reinterpret_cast<float4*>(xhat + (size_t)row * D)[f4] = oh;
        if (idx_out)
            reinterpret_cast<float4*>(idx_out + (size_t)row * D)[f4] = oi;
        if (threadIdx.x == 0 && norms_out) norms_out[row] = nrm;

        a = a2; pv = pv2; nx = nx2;
    }
}

extern "C" void kernel_launch(void* const* d_in, const int* in_sizes, int n_in,
                              void* d_out, int out_size)
{
    const float* x      = (const float*)d_in[0];   // [N, d]
    const float* rotors = (const float*)d_in[2];   // [G, 8]

    const int G = in_sizes[2] / 8;        // 256
    const int d = 3 * G;                  // 768
    const int N = in_sizes[0] / d;        // 8192

    float* out   = (float*)d_out;
    float* xhat  = out;
    float* idxp  = nullptr;
    float* normp = nullptr;
    const long nd = (long)N * d;
    if ((long)out_size >= 2 * nd)     idxp  = out + nd;
    if ((long)out_size >= 2 * nd + N) normp = out + 2 * nd;

    rotor_quant_kernel<<<NBLK, 192>>>(x, rotors, xhat, idxp, normp, N);
}

// round 4
// speedup vs baseline: 1.1936x; 1.0107x over previous
#include <cuda_runtime.h>
#include <math.h>

// RotorQuantMSE — R4: group-aligned threads (12 consecutive floats = 4 whole
// groups per thread), smem transpose staging dense<->strided (conflict-free),
// persistent blocks with 4 per-thread rotation matrices in registers.
// Block = 256 threads = 4 rows/iter (64 threads per 768-float row).

#define D 768
#define NBLK 592   // 148 SMs * 4

__device__ __forceinline__ void rotor_apply(
    float r0, float b1, float b2, float b3,
    float v1, float v2, float v3,
    float& o1, float& o2, float& o3)
{
    float t1 = fmaf(r0, v1, fmaf(b1, v2,  b2 * v3));
    float t2 = fmaf(r0, v2, fmaf(-b1, v1, b3 * v3));
    float t3 = fmaf(r0, v3, fmaf(-b2, v1, -b3 * v2));
    float t7 = fmaf(b1, v3, fmaf(-b2, v2,  b3 * v1));
    o1 = fmaf(r0, t1, fmaf( b1, t2, fmaf( b2, t3,  b3 * t7)));
    o2 = fmaf(r0, t2, fmaf(-b1, t1, fmaf( b3, t3, -b2 * t7)));
    o3 = fmaf(r0, t3, fmaf(-b2, t1, fmaf(-b3, t2,  b1 * t7)));
}

__device__ __forceinline__ void build_mat(const float* __restrict__ rp, float M[9])
{
    float r0 = __ldg(rp + 0);
    float4 bv = __ldg(reinterpret_cast<const float4*>(rp + 4));
    float b1 = bv.x, b2 = bv.y, b3 = bv.z;
    // columns = sandwich of basis vectors; y_i = sum_j M[3i+j] v_j
    rotor_apply(r0, b1, b2, b3, 1.f, 0.f, 0.f, M[0], M[3], M[6]);
    rotor_apply(r0, b1, b2, b3, 0.f, 1.f, 0.f, M[1], M[4], M[7]);
    rotor_apply(r0, b1, b2, b3, 0.f, 0.f, 1.f, M[2], M[5], M[8]);
}

__global__ void __launch_bounds__(256, 3)
rotor_quant_kernel(const float* __restrict__ x,
                   const float* __restrict__ rotors,
                   float* __restrict__ xhat,
                   float* __restrict__ idx_out,
                   float* __restrict__ norms_out,
                   int N)
{
    const int tid = threadIdx.x;
    const int s   = tid >> 6;          // row slot 0..3 (warps never span slots)
    const int t   = tid & 63;          // thread within row; owns floats 12t..12t+11
    const int wir = t >> 5;            // warp-in-row 0..1

    __shared__ float srow[4][D];       // input stage, then xhat stage
    __shared__ float sidx[4][D];
    __shared__ float spart[4][2];

    // 4 rotation matrices for groups 4t..4t+3, fixed across all rows
    float M0[9], M1[9], M2[9], M3[9];
    build_mat(rotors + (size_t)(4 * t + 0) * 8, M0);
    build_mat(rotors + (size_t)(4 * t + 1) * 8, M1);
    build_mat(rotors + (size_t)(4 * t + 2) * 8, M2);
    build_mat(rotors + (size_t)(4 * t + 3) * 8, M3);

    const float step = 2.0f / 15.0f;

    // prologue: dense load of first row (positions t, t+64, t+128 in float4s)
    int base = blockIdx.x * 4;
    float4 L0, L1, L2;
    {
        const float4* px = reinterpret_cast<const float4*>(x + (size_t)(base + s) * D);
        L0 = __ldg(px + t); L1 = __ldg(px + t + 64); L2 = __ldg(px + t + 128);
    }

    for (; base < N; base += NBLK * 4) {
        const int row = base + s;      // always < N (N multiple of 4)

        // norm partial over own 12 dense floats + warp reduce
        float sq =           fmaf(L0.x, L0.x, fmaf(L0.y, L0.y, fmaf(L0.z, L0.z, L0.w * L0.w)));
        sq = fmaf(L1.x, L1.x, fmaf(L1.y, L1.y, fmaf(L1.z, L1.z, fmaf(L1.w, L1.w, sq))));
        sq = fmaf(L2.x, L2.x, fmaf(L2.y, L2.y, fmaf(L2.z, L2.z, fmaf(L2.w, L2.w, sq))));
        #pragma unroll
        for (int o = 16; o; o >>= 1) sq += __shfl_xor_sync(0xffffffffu, sq, o);
        if ((t & 31) == 0) spart[s][wir] = sq;

        // stage input dense
        float4* st4 = reinterpret_cast<float4*>(srow[s]);
        st4[t] = L0; st4[t + 64] = L1; st4[t + 128] = L2;
        __syncthreads();

        // strided read: 12 consecutive floats (bytes 48t, 16B-aligned, conflict-free)
        const float4* sp = reinterpret_cast<const float4*>(srow[s] + 12 * t);
        float4 V0 = sp[0], V1 = sp[1], V2 = sp[2];
        const float v[12] = { V0.x, V0.y, V0.z, V0.w,
                              V1.x, V1.y, V1.z, V1.w,
                              V2.x, V2.y, V2.z, V2.w };

        const float nrm = fmaxf(sqrtf(spart[s][0] + spart[s][1]), 1e-8f);
        const float inv = 1.0f / nrm;
        const float c1  = 7.5f * inv;       // u = yraw*c1 + 7.0 == ((y/nrm)+1)*7.5 - 0.5
        const float qs  = step * nrm;       // q*nrm = fk*qs - nrm
        const float qb  = -nrm;

        // prefetch next row
        const int nb = base + NBLK * 4;
        if (nb < N) {
            const float4* px = reinterpret_cast<const float4*>(x + (size_t)(nb + s) * D);
            L0 = __ldg(px + t); L1 = __ldg(px + t + 64); L2 = __ldg(px + t + 128);
        }

        float h[12], fk[12];
        const float* Ms[4] = { M0, M1, M2, M3 };
        #pragma unroll
        for (int g = 0; g < 4; g++) {
            const float* M = Ms[g];
            const float a0 = v[3*g], a1 = v[3*g+1], a2 = v[3*g+2];
            // forward rotation (raw, norm folded into u)
            float y0 = fmaf(M[0], a0, fmaf(M[1], a1, M[2] * a2));
            float y1 = fmaf(M[3], a0, fmaf(M[4], a1, M[5] * a2));
            float y2 = fmaf(M[6], a0, fmaf(M[7], a1, M[8] * a2));
            // quantize: k = clamp(ceil(u),0,15), u = y*c1 + 7.0 (float-only path)
            float f0 = ceilf(fminf(fmaxf(fmaf(y0, c1, 7.0f), 0.0f), 15.0f));
            float f1 = ceilf(fminf(fmaxf(fmaf(y1, c1, 7.0f), 0.0f), 15.0f));
            float f2 = ceilf(fminf(fmaxf(fmaf(y2, c1, 7.0f), 0.0f), 15.0f));
            fk[3*g] = f0; fk[3*g+1] = f1; fk[3*g+2] = f2;
            // dequant scaled by nrm
            float q0 = fmaf(f0, qs, qb);
            float q1 = fmaf(f1, qs, qb);
            float q2 = fmaf(f2, qs, qb);
            // inverse rotation = M^T
            h[3*g]   = fmaf(M[0], q0, fmaf(M[3], q1, M[6] * q2));
            h[3*g+1] = fmaf(M[1], q0, fmaf(M[4], q1, M[7] * q2));
            h[3*g+2] = fmaf(M[2], q0, fmaf(M[5], q1, M[8] * q2));
        }

        // stage outputs strided (own bytes 48t — no cross-thread hazard)
        float4* op = reinterpret_cast<float4*>(srow[s] + 12 * t);
        op[0] = make_float4(h[0], h[1], h[2],  h[3]);
        op[1] = make_float4(h[4], h[5], h[6],  h[7]);
        op[2] = make_float4(h[8], h[9], h[10], h[11]);
        float4* ip = reinterpret_cast<float4*>(sidx[s] + 12 * t);
        ip[0] = make_float4(fk[0], fk[1], fk[2],  fk[3]);
        ip[1] = make_float4(fk[4], fk[5], fk[6],  fk[7]);
        ip[2] = make_float4(fk[8], fk[9], fk[10], fk[11]);
        __syncthreads();

        // dense global stores
        float4* po = reinterpret_cast<float4*>(xhat + (size_t)row * D);
        const float4* so = reinterpret_cast<const float4*>(srow[s]);
        po[t] = so[t]; po[t + 64] = so[t + 64]; po[t + 128] = so[t + 128];
        if (idx_out) {
            float4* pi = reinterpret_cast<float4*>(idx_out + (size_t)row * D);
            const float4* si = reinterpret_cast<const float4*>(sidx[s]);
            pi[t] = si[t]; pi[t + 64] = si[t + 64]; pi[t + 128] = si[t + 128];
        }
        if (t == 0 && norms_out) norms_out[row] = nrm;

        __syncthreads();   // protect srow/spart reuse next iteration (few iters, cheap)
    }
}

extern "C" void kernel_launch(void* const* d_in, const int* in_sizes, int n_in,
                              void* d_out, int out_size)
{
    const float* x      = (const float*)d_in[0];   // [N, d]
    const float* rotors = (const float*)d_in[2];   // [G, 8]

    const int G = in_sizes[2] / 8;        // 256
    const int d = 3 * G;                  // 768
    const int N = in_sizes[0] / d;        // 8192

    float* out   = (float*)d_out;
    float* xhat  = out;
    float* idxp  = nullptr;
    float* normp = nullptr;
    const long nd = (long)N * d;
    if ((long)out_size >= 2 * nd)     idxp  = out + nd;
    if ((long)out_size >= 2 * nd + N) normp = out + 2 * nd;

    rotor_quant_kernel<<<NBLK, 256>>>(x, rotors, xhat, idxp, normp, N);
}